// round 7
// baseline (speedup 1.0000x reference)
#include <cuda_runtime.h>

#define Tt 64
#define Ll 64
#define Bb 128
#define Hh 64
#define NSM 148
#define NTHR 256
#define NSPLIT 4
#define TOTALW 32512   // (4096 gates + 4032 partA) * 4

// Full h history h[t][l][b][u] -- no WAR hazards.
__device__ float g_h[(size_t)Tt * Ll * Bb * Hh];
// c[l][b][u] single-buffered, L2-only access.
__device__ float g_c[(size_t)Ll * Bb * Hh];
// z partial from h_prev half: zA[l][b][256]  (live for one diagonal per l)
__device__ float g_zA[(size_t)Ll * Bb * 256];
__device__ int   g_flags[Tt * Ll];    // gates done (h published), counts to 4
__device__ int   g_flagsA[Tt * Ll];   // partA done (zA published), counts to 4
__device__ int   g_ticket;
__device__ float g_partial[Tt];

typedef unsigned long long u64;

__device__ __forceinline__ u64 pack2(float a, float b) {
    u64 r; asm("mov.b64 %0, {%1, %2};" : "=l"(r) : "f"(a), "f"(b)); return r;
}
__device__ __forceinline__ void unpack2(u64 v, float& a, float& b) {
    asm("mov.b64 {%0, %1}, %2;" : "=f"(a), "=f"(b) : "l"(v));
}
__device__ __forceinline__ void fma2(u64& acc, u64 a, u64 b) {
    asm("fma.rn.f32x2 %0, %1, %2, %0;" : "+l"(acc) : "l"(a), "l"(b));
}
__device__ __forceinline__ float sigm(float x) {
    return __fdividef(1.0f, 1.0f + __expf(-x));
}
__device__ __forceinline__ void poll4(const int* p) {
    int v;
    do { asm volatile("ld.acquire.gpu.global.b32 %0, [%1];" : "=r"(v) : "l"(p)); } while (v < NSPLIT);
}
__device__ __forceinline__ void rel_add(int* p) {
    asm volatile("red.release.gpu.global.add.s32 [%0], 1;" :: "l"(p) : "memory");
}
__device__ __forceinline__ int ng_of(int s) { return min(min(s + 1, 127 - s), 64); }
__device__ __forceinline__ int na_of(int s) {
    int d = s + 1;
    int lo = (d > 64) ? (d - 63) : 1;
    int hi = min(63, d);
    return max(0, hi - lo + 1);
}

__global__ void init_kernel() {
    int i = blockIdx.x * blockDim.x + threadIdx.x;
    if (i < Tt * Ll) { g_flags[i] = 0; g_flagsA[i] = 0; }
    if (i == 0) g_ticket = 0;
}

// Persistent dataflow kernel. Ticket types:
//   type 0 (gates): z = bias + W_x-half GEMM(64k over h_in) [+ x term if l==0]
//                   + zA (if t>0); gate math; write c,h; release g_flags.
//   type 1 (partA): zA = W_h-half GEMM(64k over h_prev); release g_flagsA.
// Global ticket order: for step s: [gates of diag s] then [partA of diag s+1].
// Every ticket's deps are strictly earlier in this order -> deadlock-free
// under dynamic (atomic counter) dispatch with any #CTAs >= 1.
__global__ void __launch_bounds__(NTHR, 1) wave_kernel(
    const float* __restrict__ x,  const float* __restrict__ W0,
    const float* __restrict__ b0, const float* __restrict__ Wl,
    const float* __restrict__ bl)
{
    __shared__ u64   Xs2[128][35];   // X dup-packed; stride 35 u64 -> conflict-free
    __shared__ float Ws[32][68];     // [k][local col j = g*16 + u]
    __shared__ int   sp[4];          // {t, l, cg, type}

    const int tid = threadIdx.x;
    const int r0  = (tid >> 3) * 4;   // 4 batch rows / thread
    const int u0  = (tid & 7) * 2;    // 2 adjacent units (of 16-unit group)

    // staging roles
    const int xrow  = tid >> 1;         // 0..127
    const int xks   = (tid & 1) * 16;   // 16-k half within 32-k chunk
    const int wk    = tid >> 3;         // 0..31  (k within chunk)
    const int wj0   = (tid & 7) * 8;    // local col start (8 cols)
    const int wgq0  = (wj0 >> 4) * 64 + (wj0 & 15);  // + cg*16 later

    // tid0 decode state (monotone ticket ids per CTA)
    int s_cur = 0, base = 0;

    for (;;) {
        if (tid == 0) {
            int w = atomicAdd(&g_ticket, 1);
            if (w >= TOTALW) { sp[3] = -1; }
            else {
                for (;;) {
                    int sc = (ng_of(s_cur) + na_of(s_cur)) * NSPLIT;
                    if (w < base + sc) break;
                    base += sc; s_cur++;
                }
                int rem = w - base;
                int ng4 = ng_of(s_cur) * NSPLIT;
                int t, l, cg, ty;
                if (rem < ng4) {
                    ty = 0; cg = rem & 3; int cell = rem >> 2;
                    int tmin = (s_cur > 63) ? (s_cur - 63) : 0;
                    t = tmin + cell; l = s_cur - t;
                } else {
                    rem -= ng4; ty = 1; cg = rem & 3; int idx = rem >> 2;
                    int d = s_cur + 1;
                    int tmin = (d > 64) ? (d - 63) : 1;
                    t = tmin + idx; l = d - t;
                }
                sp[0] = t; sp[1] = l; sp[2] = cg; sp[3] = ty;
            }
        }
        __syncthreads();                       // BAR1: params ready
        const int ty = sp[3];
        if (ty < 0) break;
        const int t = sp[0], l = sp[1], cg = sp[2];

        const bool gemm = (ty == 1) || (l > 0);
        const int  wbase = (ty == 1) ? ((l == 0) ? 1 : 64) : 0;
        const float* Wfull = (l == 0) ? W0 : (Wl + (size_t)(l - 1) * 128 * 256);
        const int wgq = wgq0 + cg * 16;

        // ---- prefetch (no dep on flags): W chunk0, bias, x/W0row0 ----
        float4 wpre0, wpre1;
        if (gemm) {
            const float* wp = Wfull + (size_t)(wbase + wk) * 256 + wgq;
            wpre0 = ((const float4*)wp)[0];
            wpre1 = ((const float4*)wp)[1];
        }
        float2 bpre[4]; float2 w0pre[4]; float xpre[4];
        if (ty == 0) {
            const float* bias = (l == 0) ? b0 : (bl + (l - 1) * 256);
            #pragma unroll
            for (int g = 0; g < 4; g++)
                bpre[g] = *(const float2*)(bias + g * 64 + cg * 16 + u0);
            if (l == 0) {
                #pragma unroll
                for (int g = 0; g < 4; g++)
                    w0pre[g] = *(const float2*)(W0 + g * 64 + cg * 16 + u0);
                #pragma unroll
                for (int i = 0; i < 4; i++)
                    xpre[i] = x[(r0 + i) * Tt + t];
            }
        }

        // ---- acquire deps ----
        if (tid == 0) {
            if (ty == 0) {
                if (l > 0) poll4(&g_flags[t * Ll + (l - 1)]);
                if (t > 0) poll4(&g_flagsA[t * Ll + l]);
            } else {
                poll4(&g_flags[(t - 1) * Ll + l]);
            }
        }
        __syncthreads();                       // BAR2: deps ready

        // ---- seed accumulators ----
        u64 acc[4][4];
        #pragma unroll
        for (int g = 0; g < 4; g++) {
            u64 bs = (ty == 0) ? pack2(bpre[g].x, bpre[g].y) : 0ULL;
            #pragma unroll
            for (int i = 0; i < 4; i++) acc[i][g] = bs;
        }

        if (gemm) {
            const float* hs = (ty == 1)
                ? (g_h + ((size_t)(t - 1) * Ll + l) * Bb * Hh)
                : (g_h + ((size_t)t * Ll + (l - 1)) * Bb * Hh);

            // ---- chunk 0: load X, stage X+W ----
            {
                const float4* xp = (const float4*)(hs + xrow * Hh + xks);
                float4 a = xp[0], b = xp[1], c = xp[2], d = xp[3];
                float xv[16] = {a.x,a.y,a.z,a.w, b.x,b.y,b.z,b.w,
                                c.x,c.y,c.z,c.w, d.x,d.y,d.z,d.w};
                #pragma unroll
                for (int q = 0; q < 16; q++)
                    Xs2[xrow][xks + q] = pack2(xv[q], xv[q]);
                *(float4*)&Ws[wk][wj0]     = wpre0;
                *(float4*)&Ws[wk][wj0 + 4] = wpre1;
            }
            __syncthreads();                   // BAR3: stage0 ready

            // ---- prefetch chunk 1 while computing chunk 0 ----
            float4 xn0, xn1, xn2, xn3, wn0, wn1;
            {
                const float4* xp = (const float4*)(hs + xrow * Hh + 32 + xks);
                xn0 = xp[0]; xn1 = xp[1]; xn2 = xp[2]; xn3 = xp[3];
                const float* wp = Wfull + (size_t)(wbase + 32 + wk) * 256 + wgq;
                wn0 = ((const float4*)wp)[0];
                wn1 = ((const float4*)wp)[1];
            }

            #pragma unroll 16
            for (int k = 0; k < 32; k++) {
                u64 b2[4], a2[4];
                #pragma unroll
                for (int g = 0; g < 4; g++) b2[g] = *(const u64*)&Ws[k][g * 16 + u0];
                #pragma unroll
                for (int i = 0; i < 4; i++) a2[i] = Xs2[r0 + i][k];
                #pragma unroll
                for (int i = 0; i < 4; i++)
                    #pragma unroll
                    for (int g = 0; g < 4; g++) fma2(acc[i][g], a2[i], b2[g]);
            }
            __syncthreads();                   // BAR4: chunk0 reads done

            {
                float xv[16] = {xn0.x,xn0.y,xn0.z,xn0.w, xn1.x,xn1.y,xn1.z,xn1.w,
                                xn2.x,xn2.y,xn2.z,xn2.w, xn3.x,xn3.y,xn3.z,xn3.w};
                #pragma unroll
                for (int q = 0; q < 16; q++)
                    Xs2[xrow][xks + q] = pack2(xv[q], xv[q]);
                *(float4*)&Ws[wk][wj0]     = wn0;
                *(float4*)&Ws[wk][wj0 + 4] = wn1;
            }
            __syncthreads();                   // BAR5: stage1 ready

            #pragma unroll 16
            for (int k = 0; k < 32; k++) {
                u64 b2[4], a2[4];
                #pragma unroll
                for (int g = 0; g < 4; g++) b2[g] = *(const u64*)&Ws[k][g * 16 + u0];
                #pragma unroll
                for (int i = 0; i < 4; i++) a2[i] = Xs2[r0 + i][k];
                #pragma unroll
                for (int i = 0; i < 4; i++)
                    #pragma unroll
                    for (int g = 0; g < 4; g++) fma2(acc[i][g], a2[i], b2[g]);
            }
        } else {
            // gates ticket, l==0: z += x * W0[row 0]
            #pragma unroll
            for (int i = 0; i < 4; i++) {
                u64 a2 = pack2(xpre[i], xpre[i]);
                #pragma unroll
                for (int g = 0; g < 4; g++)
                    fma2(acc[i][g], a2, pack2(w0pre[g].x, w0pre[g].y));
            }
        }

        if (ty == 1) {
            // ---- partA epilogue: publish zA ----
            float* za = g_zA + (size_t)l * Bb * 256;
            #pragma unroll
            for (int i = 0; i < 4; i++) {
                int row = r0 + i;
                #pragma unroll
                for (int g = 0; g < 4; g++) {
                    float z0, z1; unpack2(acc[i][g], z0, z1);
                    __stcg((float2*)(za + row * 256 + g * 64 + cg * 16 + u0),
                           make_float2(z0, z1));
                }
            }
            __syncthreads();                   // all stores issued before release
            if (tid == 0) rel_add(&g_flagsA[t * Ll + l]);
        } else {
            // ---- gates epilogue ----
            const float* za = g_zA + (size_t)l * Bb * 256;
            float* cptr = &g_c[(size_t)l * Bb * Hh];
            float* hout = &g_h[((size_t)t * Ll + l) * Bb * Hh];
            #pragma unroll
            for (int i = 0; i < 4; i++) {
                int row = r0 + i;
                int off = row * Hh + cg * 16 + u0;
                float zi0, zi1, zj0, zj1, zf0, zf1, zo0, zo1;
                unpack2(acc[i][0], zi0, zi1);
                unpack2(acc[i][1], zj0, zj1);
                unpack2(acc[i][2], zf0, zf1);
                unpack2(acc[i][3], zo0, zo1);
                float cp0 = 0.f, cp1 = 0.f;
                if (t > 0) {
                    const float* zr = za + row * 256 + cg * 16 + u0;
                    float2 q0 = __ldcg((const float2*)(zr));
                    float2 q1 = __ldcg((const float2*)(zr + 64));
                    float2 q2 = __ldcg((const float2*)(zr + 128));
                    float2 q3 = __ldcg((const float2*)(zr + 192));
                    zi0 += q0.x; zi1 += q0.y;
                    zj0 += q1.x; zj1 += q1.y;
                    zf0 += q2.x; zf1 += q2.y;
                    zo0 += q3.x; zo1 += q3.y;
                    float2 cp = __ldcg((const float2*)(cptr + off));
                    cp0 = cp.x; cp1 = cp.y;
                }
                float c20 = cp0 * sigm(zf0) + sigm(zi0) * tanhf(zj0);
                float c21 = cp1 * sigm(zf1) + sigm(zi1) * tanhf(zj1);
                float h20 = tanhf(c20) * sigm(zo0);
                float h21 = tanhf(c21) * sigm(zo1);
                __stcg((float2*)(cptr + off), make_float2(c20, c21));
                *(float2*)(hout + off) = make_float2(h20, h21);
            }
            __syncthreads();                   // all stores issued before release
            if (tid == 0) rel_add(&g_flags[t * Ll + l]);
        }
    }
}

// pred[b,t] = relu(h[t][63][b][:] . Wd[t] + bd[t]); per-t squared-error partials.
__global__ void dense_kernel(const float* __restrict__ labels, const float* __restrict__ Wd,
                             const float* __restrict__ bd, float* __restrict__ out)
{
    int t = blockIdx.x;     // 0..63
    int b = threadIdx.x;    // 0..127
    __shared__ float wd[64];
    __shared__ float red[128];
    if (b < 64) wd[b] = Wd[t * 64 + b];
    __syncthreads();
    const float* hrow = &g_h[(((size_t)t * Ll + 63) * Bb + b) * Hh];
    float acc = 0.f;
    #pragma unroll
    for (int u = 0; u < 64; u++) acc += hrow[u] * wd[u];
    float p = acc + bd[t];
    p = (p > 0.f) ? p : 0.f;
    out[b * 64 + t] = p;
    float e = labels[b * 64 + t] - p;
    red[b] = e * e;
    __syncthreads();
    for (int s = 64; s > 0; s >>= 1) {
        if (b < s) red[b] += red[b + s];
        __syncthreads();
    }
    if (b == 0) g_partial[t] = red[0];
}

__global__ void loss_kernel(float* out, int out_size)
{
    __shared__ float red[64];
    int tid = threadIdx.x;
    red[tid] = g_partial[tid];
    __syncthreads();
    for (int s = 32; s > 0; s >>= 1) {
        if (tid < s) red[tid] += red[tid + s];
        __syncthreads();
    }
    if (tid == 0 && out_size > Bb * Tt) out[Bb * Tt] = red[0] / (float)(Bb * Tt);
}

extern "C" void kernel_launch(void* const* d_in, const int* in_sizes, int n_in,
                              void* d_out, int out_size) {
    const float* x      = (const float*)d_in[0];
    const float* labels = (const float*)d_in[1];
    const float* W0     = (const float*)d_in[2];
    const float* b0     = (const float*)d_in[3];
    const float* Wl     = (const float*)d_in[4];
    const float* bl     = (const float*)d_in[5];
    const float* Wd     = (const float*)d_in[6];
    const float* bd     = (const float*)d_in[7];
    float* out = (float*)d_out;

    init_kernel<<<16, 256>>>();
    wave_kernel<<<NSM, NTHR>>>(x, W0, b0, Wl, bl);
    dense_kernel<<<64, 128>>>(labels, Wd, bd, out);
    loss_kernel<<<1, 64>>>(out, out_size);
}

// round 8
// speedup vs baseline: 1.0186x; 1.0186x over previous
#include <cuda_runtime.h>

#define Tt 64
#define Ll 64
#define Bb 128
#define Hh 64
#define NSM 148
#define NTHR 256
#define NSPLIT 4
#define NTICK (Tt * Ll * NSPLIT)

#define XS_STRIDE 132
#define WS_STRIDE 68
#define SMEM_BYTES (128 * XS_STRIDE * 4 + 128 * WS_STRIDE * 4 + 64)

// Full h history h[t][l][b][u] -- no WAR hazards.
__device__ float g_h[(size_t)Tt * Ll * Bb * Hh];
// c[l][b][u] single-buffered, L2-only access.
__device__ float g_c[(size_t)Ll * Bb * Hh];
__device__ int   g_flags[Tt * Ll];
__device__ float g_partial[Tt];

typedef unsigned long long u64;

__device__ __forceinline__ u64 pack2(float a, float b) {
    u64 r; asm("mov.b64 %0, {%1, %2};" : "=l"(r) : "f"(a), "f"(b)); return r;
}
__device__ __forceinline__ void unpack2(u64 v, float& a, float& b) {
    asm("mov.b64 {%0, %1}, %2;" : "=f"(a), "=f"(b) : "l"(v));
}
__device__ __forceinline__ void fma2(u64& acc, u64 a, u64 b) {
    asm("fma.rn.f32x2 %0, %1, %2, %0;" : "+l"(acc) : "l"(a), "l"(b));
}
__device__ __forceinline__ float sigm(float x) {
    return __fdividef(1.0f, 1.0f + __expf(-x));
}
__device__ __forceinline__ void poll4(const int* p) {
    int v;
    do { asm volatile("ld.acquire.gpu.global.b32 %0, [%1];" : "=r"(v) : "l"(p)); } while (v < NSPLIT);
}
__device__ __forceinline__ void rel_add(int* p) {
    asm volatile("red.release.gpu.global.add.s32 [%0], 1;" :: "l"(p) : "memory");
}

__global__ void init_kernel() {
    int i = blockIdx.x * blockDim.x + threadIdx.x;
    if (i < Tt * Ll) g_flags[i] = 0;
}

// Persistent wavefront kernel, 4 CTAs per cell (cg = 16-unit group of each gate,
// 64 output cols per CTA). Static diag-major ticket striding (deadlock-free).
// Per ticket: W tile staged to smem BEFORE the dep spin; X tile staged fully
// after deps; one uninterrupted 128-k FMA loop; 4 barriers total.
__global__ void __launch_bounds__(NTHR, 1) wave_kernel(
    const float* __restrict__ x,  const float* __restrict__ W0,
    const float* __restrict__ b0, const float* __restrict__ Wl,
    const float* __restrict__ bl)
{
    extern __shared__ float smem[];
    float* Xs = smem;                       // [128][XS_STRIDE]
    float* Ws = smem + 128 * XS_STRIDE;     // [128][WS_STRIDE]  (col j = g*16+u)

    const int tid = threadIdx.x;
    const int r0  = (tid >> 3) * 4;   // 4 batch rows / thread
    const int u0  = (tid & 7) * 2;    // 2 adjacent units (of 16-unit group)

    const int srow = tid >> 1;        // staging row (X and W), 0..127
    const int shalf = tid & 1;

    for (int w = blockIdx.x; w < NTICK; w += gridDim.x) {
        // ---- decode ticket -> (t, l, cg), diagonal-major ----
        int rem = w, d = 0;
        for (;; ++d) {
            int nd4 = min(min(d + 1, 127 - d), 64) * NSPLIT;
            if (rem < nd4) break;
            rem -= nd4;
        }
        const int cg   = rem & 3;
        const int cell = rem >> 2;
        const int t    = ((d > 63) ? (d - 63) : 0) + cell;
        const int l    = d - t;

        __syncthreads();   // BAR1: prev iter fully done; smem reusable

        // ---- stage W tile (no deps -> overlaps the spin below) ----
        if (l > 0) {
            const float* wrow = Wl + (size_t)(l - 1) * 128 * 256 + (size_t)srow * 256;
            float* dst = Ws + srow * WS_STRIDE + shalf * 32;
            #pragma unroll
            for (int e = 0; e < 2; e++) {
                const float4* s4 = (const float4*)(wrow + (shalf * 2 + e) * 64 + cg * 16);
                float4* d4 = (float4*)(dst + e * 16);
                #pragma unroll
                for (int q = 0; q < 4; q++) d4[q] = s4[q];
            }
        } else {
            // W0 rows 0..64 valid; rows 65..67 zero; rows >=68 never read
            if (srow < 68) {
                float* dst = Ws + srow * WS_STRIDE + shalf * 32;
                if (srow < 65) {
                    const float* wrow = W0 + (size_t)srow * 256;
                    #pragma unroll
                    for (int e = 0; e < 2; e++) {
                        const float4* s4 = (const float4*)(wrow + (shalf * 2 + e) * 64 + cg * 16);
                        float4* d4 = (float4*)(dst + e * 16);
                        #pragma unroll
                        for (int q = 0; q < 4; q++) d4[q] = s4[q];
                    }
                } else {
                    float4 z = make_float4(0.f, 0.f, 0.f, 0.f);
                    float4* d4 = (float4*)dst;
                    #pragma unroll
                    for (int q = 0; q < 8; q++) d4[q] = z;
                }
            }
        }

        // bias prefetch
        float2 bpre[4];
        {
            const float* bias = (l == 0) ? b0 : (bl + (l - 1) * 256);
            #pragma unroll
            for (int g = 0; g < 4; g++)
                bpre[g] = *(const float2*)(bias + g * 64 + cg * 16 + u0);
        }

        // ---- acquire deps (two warps poll in parallel) ----
        if (tid == 0  && l > 0) poll4(&g_flags[t * Ll + (l - 1)]);
        if (tid == 32 && t > 0) poll4(&g_flags[(t - 1) * Ll + l]);
        __syncthreads();   // BAR2: deps ready (+ W tile staged)

        const float* hin_base   = (l > 0) ? &g_h[((size_t)t * Ll + (l - 1)) * Bb * Hh] : (const float*)0;
        const float* hprev_base = (t > 0) ? &g_h[((size_t)(t - 1) * Ll + l) * Bb * Hh] : (const float*)0;

        // ---- stage X tile ----
        int nk;
        if (l > 0) {
            nk = (t > 0) ? 128 : 64;
            // cols [0,64) = h_in ; cols [64,128) = h_prev (only if t>0)
            const float* src = (shalf == 0) ? (hin_base + srow * Hh)
                                            : (t > 0 ? hprev_base + srow * Hh : (const float*)0);
            if (src) {
                float* dst = Xs + srow * XS_STRIDE + shalf * 64;
                #pragma unroll
                for (int q = 0; q < 16; q++)
                    ((float4*)dst)[q] = ((const float4*)src)[q];
            }
        } else {
            nk = 68;
            // col 0 = x ; cols [1,65) = h_prev ; cols [65,68) = 0
            float* dst = Xs + srow * XS_STRIDE;
            int c0 = shalf * 34;
            #pragma unroll 2
            for (int c = c0; c < c0 + 34; c++) {
                float v = 0.f;
                if (c == 0) v = x[srow * Tt + t];
                else if (c < 65 && t > 0) v = hprev_base[srow * Hh + (c - 1)];
                dst[c] = v;
            }
        }
        __syncthreads();   // BAR3: X staged

        // ---- accumulators seeded with bias ----
        u64 acc[4][4];
        #pragma unroll
        for (int g = 0; g < 4; g++) {
            u64 bs = pack2(bpre[g].x, bpre[g].y);
            #pragma unroll
            for (int i = 0; i < 4; i++) acc[i][g] = bs;
        }

        // ---- uninterrupted FMA loop over nk ----
        #pragma unroll 2
        for (int k4 = 0; k4 < nk; k4 += 4) {
            float4 av[4];
            #pragma unroll
            for (int i = 0; i < 4; i++)
                av[i] = *(const float4*)&Xs[(r0 + i) * XS_STRIDE + k4];
            #pragma unroll
            for (int q = 0; q < 4; q++) {
                u64 b2[4];
                const float* wr = Ws + (k4 + q) * WS_STRIDE + u0;
                #pragma unroll
                for (int g = 0; g < 4; g++)
                    b2[g] = *(const u64*)(wr + g * 16);
                #pragma unroll
                for (int i = 0; i < 4; i++) {
                    float a = ((const float*)&av[i])[q];
                    u64 a2 = pack2(a, a);
                    #pragma unroll
                    for (int g = 0; g < 4; g++) fma2(acc[i][g], a2, b2[g]);
                }
            }
        }

        // ---- gates epilogue (thread-local i/j/f/o for its 2 units) ----
        float* cptr = &g_c[(size_t)l * Bb * Hh];
        float* hout = &g_h[((size_t)t * Ll + l) * Bb * Hh];
        #pragma unroll
        for (int i = 0; i < 4; i++) {
            int row = r0 + i;
            int off = row * Hh + cg * 16 + u0;
            float zi0, zi1, zj0, zj1, zf0, zf1, zo0, zo1;
            unpack2(acc[i][0], zi0, zi1);
            unpack2(acc[i][1], zj0, zj1);
            unpack2(acc[i][2], zf0, zf1);
            unpack2(acc[i][3], zo0, zo1);
            float cp0 = 0.f, cp1 = 0.f;
            if (t > 0) {
                float2 cp = __ldcg((const float2*)(cptr + off));
                cp0 = cp.x; cp1 = cp.y;
            }
            float c20 = cp0 * sigm(zf0) + sigm(zi0) * tanhf(zj0);
            float c21 = cp1 * sigm(zf1) + sigm(zi1) * tanhf(zj1);
            float h20 = tanhf(c20) * sigm(zo0);
            float h21 = tanhf(c21) * sigm(zo1);
            __stcg((float2*)(cptr + off), make_float2(c20, c21));
            *(float2*)(hout + off) = make_float2(h20, h21);
        }

        // ---- release ----
        __syncthreads();   // BAR4: all stores issued
        if (tid == 0) rel_add(&g_flags[t * Ll + l]);
    }
}

// pred[b,t] = relu(h[t][63][b][:] . Wd[t] + bd[t]); per-t squared-error partials.
__global__ void dense_kernel(const float* __restrict__ labels, const float* __restrict__ Wd,
                             const float* __restrict__ bd, float* __restrict__ out)
{
    int t = blockIdx.x;     // 0..63
    int b = threadIdx.x;    // 0..127
    __shared__ float wd[64];
    __shared__ float red[128];
    if (b < 64) wd[b] = Wd[t * 64 + b];
    __syncthreads();
    const float* hrow = &g_h[(((size_t)t * Ll + 63) * Bb + b) * Hh];
    float acc = 0.f;
    #pragma unroll
    for (int u = 0; u < 64; u++) acc += hrow[u] * wd[u];
    float p = acc + bd[t];
    p = (p > 0.f) ? p : 0.f;
    out[b * 64 + t] = p;
    float e = labels[b * 64 + t] - p;
    red[b] = e * e;
    __syncthreads();
    for (int s = 64; s > 0; s >>= 1) {
        if (b < s) red[b] += red[b + s];
        __syncthreads();
    }
    if (b == 0) g_partial[t] = red[0];
}

__global__ void loss_kernel(float* out, int out_size)
{
    __shared__ float red[64];
    int tid = threadIdx.x;
    red[tid] = g_partial[tid];
    __syncthreads();
    for (int s = 32; s > 0; s >>= 1) {
        if (tid < s) red[tid] += red[tid + s];
        __syncthreads();
    }
    if (tid == 0 && out_size > Bb * Tt) out[Bb * Tt] = red[0] / (float)(Bb * Tt);
}

extern "C" void kernel_launch(void* const* d_in, const int* in_sizes, int n_in,
                              void* d_out, int out_size) {
    const float* x      = (const float*)d_in[0];
    const float* labels = (const float*)d_in[1];
    const float* W0     = (const float*)d_in[2];
    const float* b0     = (const float*)d_in[3];
    const float* Wl     = (const float*)d_in[4];
    const float* bl     = (const float*)d_in[5];
    const float* Wd     = (const float*)d_in[6];
    const float* bd     = (const float*)d_in[7];
    float* out = (float*)d_out;

    cudaFuncSetAttribute(wave_kernel, cudaFuncAttributeMaxDynamicSharedMemorySize, SMEM_BYTES);

    init_kernel<<<16, 256>>>();
    wave_kernel<<<NSM, NTHR, SMEM_BYTES>>>(x, W0, b0, Wl, bl);
    dense_kernel<<<64, 128>>>(labels, Wd, bd, out);
    loss_kernel<<<1, 64>>>(out, out_size);
}

// round 9
// speedup vs baseline: 1.1624x; 1.1411x over previous
#include <cuda_runtime.h>

#define Tt 64
#define Ll 64
#define Bb 128
#define Hh 64
#define NSM 148
#define NTHR 256
#define NSPLIT 4
#define NTICK (Tt * Ll * NSPLIT)

#define XS_STRIDE 132
#define WS_STRIDE 68
#define SMEM_BYTES (128 * XS_STRIDE * 4 + 128 * WS_STRIDE * 4)

// Full h history h[t][l][b][u] -- no WAR hazards.
__device__ float g_h[(size_t)Tt * Ll * Bb * Hh];
// c[l][b][u] single-buffered, L2-only access.
__device__ float g_c[(size_t)Ll * Bb * Hh];
__device__ int   g_flags[Tt * Ll];
__device__ float g_partial[Tt];

typedef unsigned long long u64;

__device__ __forceinline__ u64 pack2(float a, float b) {
    u64 r; asm("mov.b64 %0, {%1, %2};" : "=l"(r) : "f"(a), "f"(b)); return r;
}
__device__ __forceinline__ void unpack2(u64 v, float& a, float& b) {
    asm("mov.b64 {%0, %1}, %2;" : "=f"(a), "=f"(b) : "l"(v));
}
__device__ __forceinline__ void fma2(u64& acc, u64 a, u64 b) {
    asm("fma.rn.f32x2 %0, %1, %2, %0;" : "+l"(acc) : "l"(a), "l"(b));
}
__device__ __forceinline__ float sigm(float x) {
    return __fdividef(1.0f, 1.0f + __expf(-x));
}
__device__ __forceinline__ int ldacq(const int* p) {
    int v; asm volatile("ld.acquire.gpu.global.b32 %0, [%1];" : "=r"(v) : "l"(p)); return v;
}
__device__ __forceinline__ void poll4(const int* p) {
    while (ldacq(p) < NSPLIT) { }
}
__device__ __forceinline__ void rel_add(int* p) {
    asm volatile("red.release.gpu.global.add.s32 [%0], 1;" :: "l"(p) : "memory");
}

__global__ void init_kernel() {
    int i = blockIdx.x * blockDim.x + threadIdx.x;
    if (i < Tt * Ll) g_flags[i] = 0;
}

// 64-k FMA sweep: k in [k0, k0+64), acc += Xs[row][k] * Ws[k][col]
__device__ __forceinline__ void gemm64(const float* __restrict__ Xs,
                                       const float* __restrict__ Ws,
                                       int r0, int u0, int k0, u64 acc[4][4]) {
    #pragma unroll 2
    for (int k4 = k0; k4 < k0 + 64; k4 += 4) {
        float4 av[4];
        #pragma unroll
        for (int i = 0; i < 4; i++)
            av[i] = *(const float4*)&Xs[(r0 + i) * XS_STRIDE + k4];
        #pragma unroll
        for (int q = 0; q < 4; q++) {
            u64 b2[4];
            const float* wr = Ws + (k4 + q) * WS_STRIDE + u0;
            #pragma unroll
            for (int g = 0; g < 4; g++) b2[g] = *(const u64*)(wr + g * 16);
            #pragma unroll
            for (int i = 0; i < 4; i++) {
                float a = ((const float*)&av[i])[q];
                u64 a2 = pack2(a, a);
                #pragma unroll
                for (int g = 0; g < 4; g++) fma2(acc[i][g], a2, b2[g]);
            }
        }
    }
}

// Persistent wavefront kernel, 4 CTAs per cell (64 output cols each).
// Adaptive split: the two 64-k GEMM halves (h_in <- l-flag, h_prev <- t-flag)
// execute in whichever order their flags arrive; separate accumulators keep
// the final sum order fixed => bit-deterministic output.
__global__ void __launch_bounds__(NTHR, 1) wave_kernel(
    const float* __restrict__ x,  const float* __restrict__ W0,
    const float* __restrict__ b0, const float* __restrict__ Wl,
    const float* __restrict__ bl)
{
    extern __shared__ float smem[];
    float* Xs = smem;                       // [128][XS_STRIDE] cols 0-63 h_in, 64-127 h_prev
    float* Ws = smem + 128 * XS_STRIDE;     // [128][WS_STRIDE] col j = g*16+u
    __shared__ int sh_first;

    const int tid = threadIdx.x;
    const int r0  = (tid >> 3) * 4;
    const int u0  = (tid & 7) * 2;
    const int srow = tid >> 1;
    const int shalf = tid & 1;

    for (int w = blockIdx.x; w < NTICK; w += gridDim.x) {
        // ---- decode ticket -> (t, l, cg), diagonal-major ----
        int rem = w, d = 0;
        for (;; ++d) {
            int nd4 = min(min(d + 1, 127 - d), 64) * NSPLIT;
            if (rem < nd4) break;
            rem -= nd4;
        }
        const int cg   = rem & 3;
        const int cell = rem >> 2;
        const int t    = ((d > 63) ? (d - 63) : 0) + cell;
        const int l    = d - t;

        __syncthreads();   // prev iter smem reusable

        // ---- stage W tile (no deps; overlaps the spins below) ----
        if (l > 0) {
            const float* wrow = Wl + (size_t)(l - 1) * 128 * 256 + (size_t)srow * 256;
            float* dst = Ws + srow * WS_STRIDE + shalf * 32;
            #pragma unroll
            for (int e = 0; e < 2; e++) {
                const float4* s4 = (const float4*)(wrow + (shalf * 2 + e) * 64 + cg * 16);
                float4* d4 = (float4*)(dst + e * 16);
                #pragma unroll
                for (int q = 0; q < 4; q++) d4[q] = s4[q];
            }
        } else if (srow < 68) {
            float* dst = Ws + srow * WS_STRIDE + shalf * 32;
            if (srow < 65) {
                const float* wrow = W0 + (size_t)srow * 256;
                #pragma unroll
                for (int e = 0; e < 2; e++) {
                    const float4* s4 = (const float4*)(wrow + (shalf * 2 + e) * 64 + cg * 16);
                    float4* d4 = (float4*)(dst + e * 16);
                    #pragma unroll
                    for (int q = 0; q < 4; q++) d4[q] = s4[q];
                }
            } else {
                float4 z = make_float4(0.f, 0.f, 0.f, 0.f);
                float4* d4 = (float4*)dst;
                #pragma unroll
                for (int q = 0; q < 8; q++) d4[q] = z;
            }
        }

        float2 bpre[4];
        {
            const float* bias = (l == 0) ? b0 : (bl + (l - 1) * 256);
            #pragma unroll
            for (int g = 0; g < 4; g++)
                bpre[g] = *(const float2*)(bias + g * 64 + cg * 16 + u0);
        }

        // accI seeded with bias; accP zero.  z = (bias + zI) + zP (fixed order).
        u64 accI[4][4], accP[4][4];
        #pragma unroll
        for (int g = 0; g < 4; g++) {
            u64 bs = pack2(bpre[g].x, bpre[g].y);
            #pragma unroll
            for (int i = 0; i < 4; i++) { accI[i][g] = bs; accP[i][g] = 0ULL; }
        }

        const float* hin_base   = (l > 0) ? &g_h[((size_t)t * Ll + (l - 1)) * Bb * Hh] : (const float*)0;
        const float* hprev_base = (t > 0) ? &g_h[((size_t)(t - 1) * Ll + l) * Bb * Hh] : (const float*)0;

        if (l == 0) {
            // ---- special path: GEMM over [x | h_prev | 0pad], 68 k ----
            if (tid == 0 && t > 0) poll4(&g_flags[(t - 1) * Ll + l]);
            __syncthreads();
            {
                float* dst = Xs + srow * XS_STRIDE;
                int c0 = shalf * 34;
                #pragma unroll 2
                for (int c = c0; c < c0 + 34; c++) {
                    float v = 0.f;
                    if (c == 0) v = x[srow * Tt + t];
                    else if (c < 65 && t > 0) v = hprev_base[srow * Hh + (c - 1)];
                    dst[c] = v;
                }
            }
            __syncthreads();
            // 68 k: do 64 + 4 (cols 64..67 were zero-padded in both Xs and Ws)
            gemm64(Xs, Ws, r0, u0, 0, accI);
            {
                float4 av[4];
                #pragma unroll
                for (int i = 0; i < 4; i++)
                    av[i] = *(const float4*)&Xs[(r0 + i) * XS_STRIDE + 64];
                #pragma unroll
                for (int q = 0; q < 4; q++) {
                    u64 b2[4];
                    const float* wr = Ws + (64 + q) * WS_STRIDE + u0;
                    #pragma unroll
                    for (int g = 0; g < 4; g++) b2[g] = *(const u64*)(wr + g * 16);
                    #pragma unroll
                    for (int i = 0; i < 4; i++) {
                        float a = ((const float*)&av[i])[q];
                        u64 a2 = pack2(a, a);
                        #pragma unroll
                        for (int g = 0; g < 4; g++) fma2(accI[i][g], a2, b2[g]);
                    }
                }
            }
        } else if (t == 0) {
            // ---- only h_in half ----
            if (tid == 0) poll4(&g_flags[t * Ll + (l - 1)]);
            __syncthreads();
            {
                const float4* s = (const float4*)(hin_base + srow * Hh + shalf * 32);
                float4* dt = (float4*)(Xs + srow * XS_STRIDE + shalf * 32);
                #pragma unroll
                for (int q = 0; q < 8; q++) dt[q] = s[q];
            }
            __syncthreads();
            gemm64(Xs, Ws, r0, u0, 0, accI);
        } else {
            // ---- adaptive dual-half path ----
            const int* fI = &g_flags[t * Ll + (l - 1)];
            const int* fP = &g_flags[(t - 1) * Ll + l];
            if (tid == 0) {
                int a, b;
                for (;;) {
                    a = ldacq(fI); b = ldacq(fP);
                    if (a >= NSPLIT || b >= NSPLIT) break;
                }
                sh_first = (a >= NSPLIT) ? ((b >= NSPLIT) ? 2 : 0) : 1;
            }
            __syncthreads();
            const int first = sh_first;

            if (first == 2) {
                // both ready: fused full-128k path
                {
                    const float* src = (shalf == 0) ? (hin_base + srow * Hh)
                                                    : (hprev_base + srow * Hh);
                    float* dt = Xs + srow * XS_STRIDE + shalf * 64;
                    #pragma unroll
                    for (int q = 0; q < 16; q++)
                        ((float4*)dt)[q] = ((const float4*)src)[q];
                }
                __syncthreads();
                gemm64(Xs, Ws, r0, u0, 0, accI);
                gemm64(Xs, Ws, r0, u0, 64, accP);
            } else if (first == 0) {
                // h_in first
                {
                    const float4* s = (const float4*)(hin_base + srow * Hh + shalf * 32);
                    float4* dt = (float4*)(Xs + srow * XS_STRIDE + shalf * 32);
                    #pragma unroll
                    for (int q = 0; q < 8; q++) dt[q] = s[q];
                }
                __syncthreads();
                gemm64(Xs, Ws, r0, u0, 0, accI);
                if (tid == 0) poll4(fP);
                __syncthreads();
                {
                    const float4* s = (const float4*)(hprev_base + srow * Hh + shalf * 32);
                    float4* dt = (float4*)(Xs + srow * XS_STRIDE + 64 + shalf * 32);
                    #pragma unroll
                    for (int q = 0; q < 8; q++) dt[q] = s[q];
                }
                __syncthreads();
                gemm64(Xs, Ws, r0, u0, 64, accP);
            } else {
                // h_prev first
                {
                    const float4* s = (const float4*)(hprev_base + srow * Hh + shalf * 32);
                    float4* dt = (float4*)(Xs + srow * XS_STRIDE + 64 + shalf * 32);
                    #pragma unroll
                    for (int q = 0; q < 8; q++) dt[q] = s[q];
                }
                __syncthreads();
                gemm64(Xs, Ws, r0, u0, 64, accP);
                if (tid == 0) poll4(fI);
                __syncthreads();
                {
                    const float4* s = (const float4*)(hin_base + srow * Hh + shalf * 32);
                    float4* dt = (float4*)(Xs + srow * XS_STRIDE + shalf * 32);
                    #pragma unroll
                    for (int q = 0; q < 8; q++) dt[q] = s[q];
                }
                __syncthreads();
                gemm64(Xs, Ws, r0, u0, 0, accI);
            }
        }

        // ---- gates epilogue: z = accI + accP (fixed order) ----
        float* cptr = &g_c[(size_t)l * Bb * Hh];
        float* hout = &g_h[((size_t)t * Ll + l) * Bb * Hh];
        #pragma unroll
        for (int i = 0; i < 4; i++) {
            int row = r0 + i;
            int off = row * Hh + cg * 16 + u0;
            float z0[8], z1[8];
            #pragma unroll
            for (int g = 0; g < 4; g++) {
                float iA, iB, pA, pB;
                unpack2(accI[i][g], iA, iB);
                unpack2(accP[i][g], pA, pB);
                z0[g] = iA + pA; z1[g] = iB + pB;
            }
            float cp0 = 0.f, cp1 = 0.f;
            if (t > 0) {
                float2 cp = __ldcg((const float2*)(cptr + off));
                cp0 = cp.x; cp1 = cp.y;
            }
            float c20 = cp0 * sigm(z0[2]) + sigm(z0[0]) * tanhf(z0[1]);
            float c21 = cp1 * sigm(z1[2]) + sigm(z1[0]) * tanhf(z1[1]);
            float h20 = tanhf(c20) * sigm(z0[3]);
            float h21 = tanhf(c21) * sigm(z1[3]);
            __stcg((float2*)(cptr + off), make_float2(c20, c21));
            *(float2*)(hout + off) = make_float2(h20, h21);
        }

        __syncthreads();   // all stores issued
        if (tid == 0) rel_add(&g_flags[t * Ll + l]);
    }
}

// pred[b,t] = relu(h[t][63][b][:] . Wd[t] + bd[t]); per-t squared-error partials.
__global__ void dense_kernel(const float* __restrict__ labels, const float* __restrict__ Wd,
                             const float* __restrict__ bd, float* __restrict__ out)
{
    int t = blockIdx.x;
    int b = threadIdx.x;
    __shared__ float wd[64];
    __shared__ float red[128];
    if (b < 64) wd[b] = Wd[t * 64 + b];
    __syncthreads();
    const float* hrow = &g_h[(((size_t)t * Ll + 63) * Bb + b) * Hh];
    float acc = 0.f;
    #pragma unroll
    for (int u = 0; u < 64; u++) acc += hrow[u] * wd[u];
    float p = acc + bd[t];
    p = (p > 0.f) ? p : 0.f;
    out[b * 64 + t] = p;
    float e = labels[b * 64 + t] - p;
    red[b] = e * e;
    __syncthreads();
    for (int s = 64; s > 0; s >>= 1) {
        if (b < s) red[b] += red[b + s];
        __syncthreads();
    }
    if (b == 0) g_partial[t] = red[0];
}

__global__ void loss_kernel(float* out, int out_size)
{
    __shared__ float red[64];
    int tid = threadIdx.x;
    red[tid] = g_partial[tid];
    __syncthreads();
    for (int s = 32; s > 0; s >>= 1) {
        if (tid < s) red[tid] += red[tid + s];
        __syncthreads();
    }
    if (tid == 0 && out_size > Bb * Tt) out[Bb * Tt] = red[0] / (float)(Bb * Tt);
}

extern "C" void kernel_launch(void* const* d_in, const int* in_sizes, int n_in,
                              void* d_out, int out_size) {
    const float* x      = (const float*)d_in[0];
    const float* labels = (const float*)d_in[1];
    const float* W0     = (const float*)d_in[2];
    const float* b0     = (const float*)d_in[3];
    const float* Wl     = (const float*)d_in[4];
    const float* bl     = (const float*)d_in[5];
    const float* Wd     = (const float*)d_in[6];
    const float* bd     = (const float*)d_in[7];
    float* out = (float*)d_out;

    cudaFuncSetAttribute(wave_kernel, cudaFuncAttributeMaxDynamicSharedMemorySize, SMEM_BYTES);

    init_kernel<<<16, 256>>>();
    wave_kernel<<<NSM, NTHR, SMEM_BYTES>>>(x, W0, b0, Wl, bl);
    dense_kernel<<<64, 128>>>(labels, Wd, bd, out);
    loss_kernel<<<1, 64>>>(out, out_size);
}